// round 2
// baseline (speedup 1.0000x reference)
#include <cuda_runtime.h>
#include <math.h>

// SpectralConv2d: B=8, C=64, H=W=256, modes 16x16.
// out = irfftn( pad( einsum(corner(rfftn(x)), W) ) )  -- all transforms reduced
// to dense partial-DFT stages over the 16 surviving modes per axis.

#define BATCH 8
#define CH    64
#define NIMG  (BATCH*CH)      // 512 images of 256x256

// cos/sin(2*pi*k*t/256) for k<16, t<256, layout [t][k]
__device__ float2 g_tab[256*16];
// X_ft corner per (b,i): [img][k*16+w], complex
__device__ float2 g_X[NIMG*256];
// G per (b,o): [img][k*16+w], complex
__device__ float2 g_G[NIMG*256];
// Z per (b,o): [img][p][j], j<16: cos-coeff, j>=16: sin-coeff
__device__ float  g_Z[(size_t)NIMG*256*32];

// ---------------- table init (runs every launch; deterministic) -------------
__global__ void k_init() {
    int i = blockIdx.x * blockDim.x + threadIdx.x;
    if (i >= 4096) return;
    int t = i >> 4, k = i & 15;
    int m = (t * k) & 255;
    double s, c;
    sincospi((double)m / 128.0, &s, &c);   // angle = 2*pi*m/256
    g_tab[i] = make_float2((float)c, (float)s);
}

// ---------------- K1: x -> A (partial DFT over H) -> corner DFT over W ------
// One block per image. Thread = one x-column for the H pass, then (k,w) for
// the W-corner pass (A kept in shared, no global round trip).
__global__ void __launch_bounds__(256) k1(const float* __restrict__ x) {
    extern __shared__ __align__(16) char smem_raw[];
    float2* s_tab = (float2*)smem_raw;            // 4096 float2 = 32KB
    float2* s_A   = (float2*)(smem_raw + 32768);  // [k][x] 4096 float2 = 32KB
    int img = blockIdx.x, tid = threadIdx.x;

    for (int i = tid; i < 4096; i += 256) s_tab[i] = g_tab[i];
    __syncthreads();

    const float* xp = x + (size_t)img * 65536 + tid;
    float ar[16], as_[16];
#pragma unroll
    for (int k = 0; k < 16; k++) { ar[k] = 0.f; as_[k] = 0.f; }

#pragma unroll 4
    for (int h = 0; h < 256; h++) {
        float v = xp[(size_t)h * 256];                       // coalesced
        const float4* t4 = (const float4*)(s_tab + h * 16);  // broadcast LDS.128
#pragma unroll
        for (int k2 = 0; k2 < 8; k2++) {
            float4 q = t4[k2];
            ar[2*k2]     = fmaf(v, q.x, ar[2*k2]);
            as_[2*k2]    = fmaf(v, q.y, as_[2*k2]);
            ar[2*k2+1]   = fmaf(v, q.z, ar[2*k2+1]);
            as_[2*k2+1]  = fmaf(v, q.w, as_[2*k2+1]);
        }
    }
    // A[k,x] = ar - i*as  (e^{-i} convention)
#pragma unroll
    for (int k = 0; k < 16; k++) s_A[k * 256 + tid] = make_float2(ar[k], as_[k]);
    __syncthreads();

    // corner DFT over x: X[k,w] = sum_x A[k,x] * e^{-i a w x}
    int k = tid >> 4, w = tid & 15;
    float xr = 0.f, xi = 0.f;
#pragma unroll 4
    for (int xx = 0; xx < 256; xx++) {
        float2 a  = s_A[k * 256 + xx];     // (ar, as), Ai = -as
        float2 cs = s_tab[xx * 16 + w];    // (cos awx, sin awx)
        xr += a.x * cs.x - a.y * cs.y;     //  ar*c - as*s
        xi -= a.y * cs.x + a.x * cs.y;     // -as*c - ar*s
    }
    g_X[img * 256 + tid] = make_float2(xr, xi);
}

// ---------------- K2b: channel mix  G[b,o] = sum_i X[b,i] * (wr + i wi) -----
__global__ void __launch_bounds__(256) k2b(const float* __restrict__ wre,
                                           const float* __restrict__ wim) {
    int b = blockIdx.x >> 6, o = blockIdx.x & 63, tid = threadIdx.x;
    const float2* Xb = g_X + b * 64 * 256;
    float gr = 0.f, gi = 0.f;
#pragma unroll 4
    for (int i = 0; i < 64; i++) {
        float2 xv = Xb[i * 256 + tid];
        float wr = wre[(size_t)(i * 64 + o) * 256 + tid];
        float wi = wim[(size_t)(i * 64 + o) * 256 + tid];
        gr = fmaf(xv.x, wr, fmaf(-xv.y, wi, gr));
        gi = fmaf(xv.x, wi, fmaf( xv.y, wr, gi));
    }
    g_G[blockIdx.x * 256 + tid] = make_float2(gr, gi);
}

// ---------------- K2c: inverse DFT over k -> Z coefficients -----------------
// Y[p,w] = (1/256) sum_k G[k,w] e^{+i a k p}; fold irfft factors into Z:
//   Zc[p,0]=Yr/256, Zs[p,0]=0;  w>=1: Zc=2Yr/256, Zs=-2Yi/256
__global__ void __launch_bounds__(256) k2c() {
    __shared__ float2 sG[256];
    int bo = blockIdx.x, p = threadIdx.x;
    sG[p] = g_G[bo * 256 + p];
    __syncthreads();

    float2 tp[16];
#pragma unroll
    for (int k = 0; k < 16; k++) tp[k] = g_tab[p * 16 + k];  // (cos akp, sin akp)

    float zc[16], zs[16];
#pragma unroll
    for (int w = 0; w < 16; w++) {
        float yr = 0.f, yi = 0.f;
#pragma unroll
        for (int k = 0; k < 16; k++) {
            float2 g = sG[k * 16 + w];
            yr += g.x * tp[k].x - g.y * tp[k].y;
            yi += g.x * tp[k].y + g.y * tp[k].x;
        }
        zc[w] = yr; zs[w] = -yi;
    }
    const float s1 = 1.0f / 65536.0f, s2 = 2.0f / 65536.0f;
    zc[0] *= s1; zs[0] = 0.f;
#pragma unroll
    for (int w = 1; w < 16; w++) { zc[w] *= s2; zs[w] *= s2; }

    float4* z4 = (float4*)(g_Z + ((size_t)bo * 256 + p) * 32);
    z4[0] = make_float4(zc[0],  zc[1],  zc[2],  zc[3]);
    z4[1] = make_float4(zc[4],  zc[5],  zc[6],  zc[7]);
    z4[2] = make_float4(zc[8],  zc[9],  zc[10], zc[11]);
    z4[3] = make_float4(zc[12], zc[13], zc[14], zc[15]);
    z4[4] = make_float4(zs[0],  zs[1],  zs[2],  zs[3]);
    z4[5] = make_float4(zs[4],  zs[5],  zs[6],  zs[7]);
    z4[6] = make_float4(zs[8],  zs[9],  zs[10], zs[11]);
    z4[7] = make_float4(zs[12], zs[13], zs[14], zs[15]);
}

// ---------------- K3: out[p,q] = sum_w Zc[p,w]cos(awq) + Zs[p,w]sin(awq) ----
// One block per image. Warp owns a q-quarter; each lane keeps the 32 basis
// values for its two q's in registers (reused across 128 p rows) -> FMA-bound.
__global__ void __launch_bounds__(256) k3(float* __restrict__ out) {
    extern __shared__ __align__(16) char smem_raw[];
    float* s_c = (float*)smem_raw;     // [w][q] 4096
    float* s_s = s_c + 4096;           // [w][q] 4096
    float* s_z = s_s + 4096;           // [p][32] 8192
    int img = blockIdx.x, tid = threadIdx.x;

    for (int i = tid; i < 4096; i += 256) {
        float2 cs = g_tab[i];
        int q = i >> 4, w = i & 15;
        s_c[w * 256 + q] = cs.x;
        s_s[w * 256 + q] = cs.y;
    }
    const float4* zsrc = (const float4*)(g_Z + (size_t)img * 8192);
    float4* zdst = (float4*)s_z;
    for (int i = tid; i < 2048; i += 256) zdst[i] = zsrc[i];
    __syncthreads();

    int warp = tid >> 5, lane = tid & 31;
    int pbase = (warp >> 2) * 128;
    int qb = (warp & 3) * 64;
    int q0 = qb + lane, q1 = qb + 32 + lane;

    float bc0[16], bs0[16], bc1[16], bs1[16];
#pragma unroll
    for (int w = 0; w < 16; w++) {
        bc0[w] = s_c[w * 256 + q0]; bs0[w] = s_s[w * 256 + q0];
        bc1[w] = s_c[w * 256 + q1]; bs1[w] = s_s[w * 256 + q1];
    }

    float* op = out + (size_t)img * 65536;
    for (int pi = 0; pi < 128; pi++) {
        int p = pbase + pi;
        const float4* z4 = (const float4*)(s_z + p * 32);
        float z[32];
#pragma unroll
        for (int t = 0; t < 8; t++) {
            float4 v = z4[t];                        // broadcast LDS.128
            z[4*t] = v.x; z[4*t+1] = v.y; z[4*t+2] = v.z; z[4*t+3] = v.w;
        }
        float acc0 = 0.f, acc1 = 0.f;
#pragma unroll
        for (int w = 0; w < 16; w++) {
            acc0 = fmaf(z[w],      bc0[w], acc0);
            acc0 = fmaf(z[16 + w], bs0[w], acc0);
            acc1 = fmaf(z[w],      bc1[w], acc1);
            acc1 = fmaf(z[16 + w], bs1[w], acc1);
        }
        op[(size_t)p * 256 + q0] = acc0;             // coalesced stores
        op[(size_t)p * 256 + q1] = acc1;
    }
}

extern "C" void kernel_launch(void* const* d_in, const int* in_sizes, int n_in,
                              void* d_out, int out_size) {
    const float* x   = (const float*)d_in[0];
    const float* wre = (const float*)d_in[1];
    const float* wim = (const float*)d_in[2];
    float* out = (float*)d_out;

    cudaFuncSetAttribute(k1, cudaFuncAttributeMaxDynamicSharedMemorySize, 65536);
    cudaFuncSetAttribute(k3, cudaFuncAttributeMaxDynamicSharedMemorySize, 65536);

    k_init<<<16, 256>>>();
    k1 <<<NIMG, 256, 65536>>>(x);
    k2b<<<NIMG, 256>>>(wre, wim);
    k2c<<<NIMG, 256>>>();
    k3 <<<NIMG, 256, 65536>>>(out);
}

// round 3
// speedup vs baseline: 1.0542x; 1.0542x over previous
#include <cuda_runtime.h>
#include <math.h>

// SpectralConv2d: B=8, C=64, H=W=256, modes 16x16.
// Dense partial-DFT stages over the 16 surviving modes per axis, with
// packed f32x2 FMA (FFMA2) on the two big stages.

#define NIMG 512              // B*C images of 256x256

typedef unsigned long long u64;

__device__ __forceinline__ u64 pk2(float lo, float hi) {
    u64 r; asm("mov.b64 %0,{%1,%2};" : "=l"(r) : "f"(lo), "f"(hi)); return r;
}
__device__ __forceinline__ float2 upk2(u64 v) {
    float2 r; asm("mov.b64 {%0,%1},%2;" : "=f"(r.x), "=f"(r.y) : "l"(v)); return r;
}
__device__ __forceinline__ void fma2(u64 &d, u64 a, u64 b) {
    asm("fma.rn.f32x2 %0,%1,%2,%0;" : "+l"(d) : "l"(a), "l"(b));
}

// cos/sin(2*pi*k*t/256), k<16, t<256
__device__ float2 g_tab[256 * 16];   // [t][k]
__device__ float2 g_tabT[16 * 256];  // [k][t]  (coalesced basis for k2 phase B)
// X_ft corner per (b,i): [img][k*16+w], complex
__device__ float2 g_X[NIMG * 256];
// Z per (b,o): [img][p][j], j<16: cos-coeff, j>=16: sin-coeff
__device__ float  g_Z[(size_t)NIMG * 256 * 32];

// ---------------- table init ------------------------------------------------
__global__ void k_init() {
    int i = blockIdx.x * blockDim.x + threadIdx.x;
    if (i >= 4096) return;
    int t = i >> 4, k = i & 15;
    int m = (t * k) & 255;
    double s, c;
    sincospi((double)m / 128.0, &s, &c);   // angle = 2*pi*m/256
    float2 v = make_float2((float)c, (float)s);
    g_tab[i] = v;
    g_tabT[k * 256 + t] = v;
}

// ---------------- K1: x -> A (partial DFT over H) -> corner DFT over W ------
__global__ void __launch_bounds__(256) k1(const float* __restrict__ x) {
    extern __shared__ __align__(16) char smem_raw[];
    float2* s_tab = (float2*)smem_raw;            // [t][k] 32KB
    float2* s_A   = (float2*)(smem_raw + 32768);  // [k][x] 32KB
    int img = blockIdx.x, tid = threadIdx.x;

    for (int i = tid; i < 4096; i += 256) s_tab[i] = g_tab[i];
    __syncthreads();

    const float* xp = x + (size_t)img * 65536 + tid;
    u64 acc[16];
#pragma unroll
    for (int k = 0; k < 16; k++) acc[k] = 0ull;   // (0.f, 0.f)

#pragma unroll 4
    for (int h = 0; h < 256; h++) {
        float v = xp[(size_t)h * 256];            // coalesced
        u64 vv = pk2(v, v);
        const float4* t4 = (const float4*)(s_tab + h * 16);   // broadcast LDS.128
#pragma unroll
        for (int k2 = 0; k2 < 8; k2++) {
            float4 q = t4[k2];                    // (c0,s0,c1,s1)
            fma2(acc[2 * k2],     vv, pk2(q.x, q.y));  // (ar,as) += (v,v)*(c,s)
            fma2(acc[2 * k2 + 1], vv, pk2(q.z, q.w));
        }
    }
    // A[k,x] = ar - i*as
#pragma unroll
    for (int k = 0; k < 16; k++) s_A[k * 256 + tid] = upk2(acc[k]);
    __syncthreads();

    // corner DFT over x: X[k,w] = sum_x A[k,x] * e^{-i a w x}
    int k = tid >> 4, w = tid & 15;
    float xr = 0.f, xi = 0.f;
#pragma unroll 4
    for (int xx = 0; xx < 256; xx++) {
        float2 a  = s_A[k * 256 + xx];            // (ar, as), Ai = -as
        float2 cs = s_tab[xx * 16 + w];
        xr += a.x * cs.x - a.y * cs.y;
        xi -= a.y * cs.x + a.x * cs.y;
    }
    g_X[img * 256 + tid] = make_float2(xr, xi);
}

// ---------------- K2 (fused): channel mix + inverse-k DFT -> Z --------------
__global__ void __launch_bounds__(256) k2(const float* __restrict__ wre,
                                          const float* __restrict__ wim) {
    __shared__ float2 sG[256];
    int b = blockIdx.x >> 6, o = blockIdx.x & 63, tid = threadIdx.x;

    // Phase A: G[k,w] = sum_i X[b,i,k,w] * (wr + i wi);   tid = k*16+w
    {
        const float2* Xb = g_X + b * 64 * 256;
        float gr = 0.f, gi = 0.f;
#pragma unroll 4
        for (int i = 0; i < 64; i++) {
            float2 xv = Xb[i * 256 + tid];
            float wr = wre[(size_t)(i * 64 + o) * 256 + tid];
            float wi = wim[(size_t)(i * 64 + o) * 256 + tid];
            gr = fmaf(xv.x, wr, fmaf(-xv.y, wi, gr));
            gi = fmaf(xv.x, wi, fmaf( xv.y, wr, gi));
        }
        sG[tid] = make_float2(gr, gi);
    }
    __syncthreads();

    // Phase B: Y[p,w] = sum_k G[k,w] e^{+i a k p};  tid = p
    int p = tid;
    float2 tp[16];
#pragma unroll
    for (int k = 0; k < 16; k++) tp[k] = g_tabT[k * 256 + p];   // coalesced

    float zc[16], zs[16];
#pragma unroll
    for (int w = 0; w < 16; w++) {
        float yr = 0.f, yi = 0.f;
#pragma unroll
        for (int k = 0; k < 16; k++) {
            float2 g = sG[k * 16 + w];            // broadcast
            yr += g.x * tp[k].x - g.y * tp[k].y;
            yi += g.x * tp[k].y + g.y * tp[k].x;
        }
        zc[w] = yr; zs[w] = -yi;
    }
    const float s1 = 1.0f / 65536.0f, s2 = 2.0f / 65536.0f;
    zc[0] *= s1; zs[0] = 0.f;
#pragma unroll
    for (int w = 1; w < 16; w++) { zc[w] *= s2; zs[w] *= s2; }

    float4* z4 = (float4*)(g_Z + ((size_t)blockIdx.x * 256 + p) * 32);
    z4[0] = make_float4(zc[0],  zc[1],  zc[2],  zc[3]);
    z4[1] = make_float4(zc[4],  zc[5],  zc[6],  zc[7]);
    z4[2] = make_float4(zc[8],  zc[9],  zc[10], zc[11]);
    z4[3] = make_float4(zc[12], zc[13], zc[14], zc[15]);
    z4[4] = make_float4(zs[0],  zs[1],  zs[2],  zs[3]);
    z4[5] = make_float4(zs[4],  zs[5],  zs[6],  zs[7]);
    z4[6] = make_float4(zs[8],  zs[9],  zs[10], zs[11]);
    z4[7] = make_float4(zs[12], zs[13], zs[14], zs[15]);
}

// ---------------- K3: out[p,q] = sum_w Zc[p,w]cos(awq) + Zs[p,w]sin(awq) ----
// f32x2 pairing over adjacent w: z-pairs come free from LDS.128; basis pairs
// packed once per lane. Horizontal add per output.
__global__ void __launch_bounds__(256) k3(float* __restrict__ out) {
    extern __shared__ __align__(16) char smem_raw[];
    float* s_c = (float*)smem_raw;     // [w][q] 16KB
    float* s_s = s_c + 4096;           // [w][q] 16KB
    float* s_z = s_s + 4096;           // [p][32] 32KB
    int img = blockIdx.x, tid = threadIdx.x;

    for (int i = tid; i < 4096; i += 256) {
        float2 cs = g_tab[i];
        int q = i >> 4, w = i & 15;
        s_c[w * 256 + q] = cs.x;
        s_s[w * 256 + q] = cs.y;
    }
    {
        const float4* zsrc = (const float4*)(g_Z + (size_t)img * 8192);
        float4* zdst = (float4*)s_z;
        for (int i = tid; i < 2048; i += 256) zdst[i] = zsrc[i];
    }
    __syncthreads();

    int warp = tid >> 5, lane = tid & 31;
    int pbase = (warp >> 2) * 128;
    int qb = (warp & 3) * 64;
    int q0 = qb + lane, q1 = qb + 32 + lane;

    u64 c0p[8], s0p[8], c1p[8], s1p[8];
#pragma unroll
    for (int w2 = 0; w2 < 8; w2++) {
        c0p[w2] = pk2(s_c[(2 * w2) * 256 + q0], s_c[(2 * w2 + 1) * 256 + q0]);
        s0p[w2] = pk2(s_s[(2 * w2) * 256 + q0], s_s[(2 * w2 + 1) * 256 + q0]);
        c1p[w2] = pk2(s_c[(2 * w2) * 256 + q1], s_c[(2 * w2 + 1) * 256 + q1]);
        s1p[w2] = pk2(s_s[(2 * w2) * 256 + q1], s_s[(2 * w2 + 1) * 256 + q1]);
    }

    float* op = out + (size_t)img * 65536;
    for (int pi = 0; pi < 128; pi++) {
        int p = pbase + pi;
        const float4* z4 = (const float4*)(s_z + p * 32);
        u64 zc[8], zs[8];
#pragma unroll
        for (int t = 0; t < 4; t++) {
            float4 v = z4[t];                     // broadcast LDS.128
            zc[2 * t] = pk2(v.x, v.y); zc[2 * t + 1] = pk2(v.z, v.w);
        }
#pragma unroll
        for (int t = 0; t < 4; t++) {
            float4 v = z4[4 + t];
            zs[2 * t] = pk2(v.x, v.y); zs[2 * t + 1] = pk2(v.z, v.w);
        }
        u64 a0 = 0ull, b0 = 0ull, a1 = 0ull, b1 = 0ull;  // two chains per q
#pragma unroll
        for (int w2 = 0; w2 < 8; w2++) {
            fma2(a0, zc[w2], c0p[w2]);
            fma2(b0, zs[w2], s0p[w2]);
            fma2(a1, zc[w2], c1p[w2]);
            fma2(b1, zs[w2], s1p[w2]);
        }
        float2 fa0 = upk2(a0), fb0 = upk2(b0), fa1 = upk2(a1), fb1 = upk2(b1);
        op[(size_t)p * 256 + q0] = (fa0.x + fa0.y) + (fb0.x + fb0.y);
        op[(size_t)p * 256 + q1] = (fa1.x + fa1.y) + (fb1.x + fb1.y);
    }
}

extern "C" void kernel_launch(void* const* d_in, const int* in_sizes, int n_in,
                              void* d_out, int out_size) {
    const float* x   = (const float*)d_in[0];
    const float* wre = (const float*)d_in[1];
    const float* wim = (const float*)d_in[2];
    float* out = (float*)d_out;

    cudaFuncSetAttribute(k1, cudaFuncAttributeMaxDynamicSharedMemorySize, 65536);
    cudaFuncSetAttribute(k3, cudaFuncAttributeMaxDynamicSharedMemorySize, 65536);

    k_init<<<16, 256>>>();
    k1 <<<NIMG, 256, 65536>>>(x);
    k2 <<<NIMG, 256>>>(wre, wim);
    k3 <<<NIMG, 256, 65536>>>(out);
}